// round 14
// baseline (speedup 1.0000x reference)
#include <cuda_runtime.h>
#include <cuda_bf16.h>
#include <cstdint>
#include <math.h>

#define T_STEPS 512
#define B_SZ    128
#define NI_SZ   512
#define D_SZ    512
#define G4_SZ   2048   // 4*D

typedef unsigned long long u64;

// Scratch (device globals: allocation-free rule workaround)
__device__ float g_intern[(size_t)T_STEPS * B_SZ * G4_SZ];
__device__ uint32_t g_hpk[2][(size_t)B_SZ * D_SZ];   // packed bf16 hi|lo h, [b][k], ping-pong
__device__ unsigned g_flag[128 * 32];                // per-CTA produce flag (128B padded)
// bf16 split planes for the phase-1 GEMM
__device__ __nv_bfloat16 g_Xh[(size_t)T_STEPS * B_SZ * NI_SZ];
__device__ __nv_bfloat16 g_Xl[(size_t)T_STEPS * B_SZ * NI_SZ];
__device__ __nv_bfloat16 g_Bh[(size_t)G4_SZ * NI_SZ];   // Wf^T hi  [n][k]
__device__ __nv_bfloat16 g_Bl[(size_t)G4_SZ * NI_SZ];   // Wf^T lo

// ---------------- helpers ----------------
__device__ __forceinline__ unsigned ld_acq(const unsigned* p) {
    unsigned v;
    asm volatile("ld.acquire.gpu.global.u32 %0, [%1];" : "=r"(v) : "l"(p) : "memory");
    return v;
}
__device__ __forceinline__ void st_release_exch(unsigned* p, unsigned v) {
    unsigned tmp;
    asm volatile("atom.release.gpu.global.exch.b32 %0, [%1], %2;"
                 : "=r"(tmp) : "l"(p), "r"(v) : "memory");
}
__device__ __forceinline__ void hmma16816(float& c0, float& c1, float& c2, float& c3,
                                          uint32_t a0, uint32_t a1, uint32_t a2, uint32_t a3,
                                          uint32_t b0, uint32_t b1) {
    asm("mma.sync.aligned.m16n8k16.row.col.f32.bf16.bf16.f32 "
        "{%0,%1,%2,%3}, {%4,%5,%6,%7}, {%8,%9}, {%0,%1,%2,%3};"
        : "+f"(c0), "+f"(c1), "+f"(c2), "+f"(c3)
        : "r"(a0), "r"(a1), "r"(a2), "r"(a3), "r"(b0), "r"(b1));
}
__device__ __forceinline__ uint32_t pack_split(float f) {
    __nv_bfloat16 hb = __float2bfloat16(f);
    float rem = f - __bfloat162float(hb);
    __nv_bfloat16 lb = __float2bfloat16(rem);
    return (uint32_t)*(unsigned short*)&hb | ((uint32_t)*(unsigned short*)&lb << 16);
}

// ---------------------------------------------------------------------------
// One-time prep kernels
// ---------------------------------------------------------------------------
__global__ __launch_bounds__(256)
void split_x_kernel(const float* __restrict__ X)
{
    size_t i4 = (size_t)blockIdx.x * 256 + threadIdx.x;
    const float4 v = ((const float4*)X)[i4];
    float f[4] = {v.x, v.y, v.z, v.w};
    unsigned short h[4], l[4];
    #pragma unroll
    for (int q = 0; q < 4; q++) {
        __nv_bfloat16 hb = __float2bfloat16(f[q]);
        float lo = f[q] - __bfloat162float(hb);
        __nv_bfloat16 lb = __float2bfloat16(lo);
        h[q] = *(unsigned short*)&hb;
        l[q] = *(unsigned short*)&lb;
    }
    ((uint2*)g_Xh)[i4] = make_uint2((unsigned)h[0] | ((unsigned)h[1] << 16),
                                    (unsigned)h[2] | ((unsigned)h[3] << 16));
    ((uint2*)g_Xl)[i4] = make_uint2((unsigned)l[0] | ((unsigned)l[1] << 16),
                                    (unsigned)l[2] | ((unsigned)l[3] << 16));
}

__global__ __launch_bounds__(256)
void split_wfT_kernel(const float* __restrict__ Wf)
{
    int idx = blockIdx.x * 256 + threadIdx.x;
    int k = idx >> 11;
    int n = idx & 2047;
    float v = Wf[(size_t)k * G4_SZ + n];
    __nv_bfloat16 hb = __float2bfloat16(v);
    float lo = v - __bfloat162float(hb);
    g_Bh[(size_t)n * NI_SZ + k] = hb;
    g_Bl[(size_t)n * NI_SZ + k] = __float2bfloat16(lo);
}

__global__ __launch_bounds__(256)
void h0_pack_kernel(const float* __restrict__ h0)
{
    int idx = blockIdx.x * 256 + threadIdx.x;   // 65536
    g_hpk[0][idx] = pack_split(h0[idx]);
}

// ---------------------------------------------------------------------------
// Phase 1: intern = X@Wf + bf via mma.sync bf16 split GEMM (R12, proven)
// ---------------------------------------------------------------------------
#define APAD 72

__global__ __launch_bounds__(256)
void gemm_mma_kernel(const float* __restrict__ bf)
{
    __shared__ __align__(16) unsigned short A_s[128 * APAD];
    __shared__ __align__(16) unsigned short B_s[128 * APAD];

    const int t = threadIdx.x;
    const int wid = t >> 5, lane = t & 31;
    const int g  = lane >> 2;
    const int tig = lane & 3;
    const int n0 = blockIdx.x * 128;
    const int m0 = blockIdx.y * 128;
    const int wm = wid & 1;
    const int wn = wid >> 1;

    float c[4][4][4];
    #pragma unroll
    for (int fm = 0; fm < 4; fm++)
        #pragma unroll
        for (int fn = 0; fn < 4; fn++)
            #pragma unroll
            for (int q = 0; q < 4; q++) c[fm][fn][q] = 0.f;

    uint4 av[4], bv[4];
    {
        #pragma unroll
        for (int u = 0; u < 4; u++) {
            int idx = u * 256 + t;
            int row = idx >> 3, kq = (idx & 7) * 8;
            av[u] = *(const uint4*)(g_Xh + (size_t)(m0 + row) * NI_SZ + kq);
            bv[u] = *(const uint4*)(g_Bh + (size_t)(n0 + row) * NI_SZ + kq);
        }
    }

    for (int ci = 0; ci < 24; ci++) {
        __syncthreads();
        #pragma unroll
        for (int u = 0; u < 4; u++) {
            int idx = u * 256 + t;
            int row = idx >> 3, kq = (idx & 7) * 8;
            *(uint4*)&A_s[row * APAD + kq] = av[u];
            *(uint4*)&B_s[row * APAD + kq] = bv[u];
        }
        __syncthreads();

        if (ci < 23) {
            int cn = ci + 1;
            int seg = cn >> 3;
            int k_in = (cn & 7) * 64;
            const __nv_bfloat16* Ap = (seg < 2) ? g_Xh : g_Xl;
            const __nv_bfloat16* Bp = (seg == 1) ? g_Bl : g_Bh;
            #pragma unroll
            for (int u = 0; u < 4; u++) {
                int idx = u * 256 + t;
                int row = idx >> 3, kq = (idx & 7) * 8;
                av[u] = *(const uint4*)(Ap + (size_t)(m0 + row) * NI_SZ + k_in + kq);
                bv[u] = *(const uint4*)(Bp + (size_t)(n0 + row) * NI_SZ + k_in + kq);
            }
        }

        #pragma unroll
        for (int ks = 0; ks < 4; ks++) {
            const int kb = ks * 16 + tig * 2;
            uint32_t afr[4][4], bfr[4][2];
            #pragma unroll
            for (int fm = 0; fm < 4; fm++) {
                int r0 = wm * 64 + fm * 16 + g;
                afr[fm][0] = *(const uint32_t*)&A_s[r0 * APAD + kb];
                afr[fm][1] = *(const uint32_t*)&A_s[(r0 + 8) * APAD + kb];
                afr[fm][2] = *(const uint32_t*)&A_s[r0 * APAD + kb + 8];
                afr[fm][3] = *(const uint32_t*)&A_s[(r0 + 8) * APAD + kb + 8];
            }
            #pragma unroll
            for (int fn = 0; fn < 4; fn++) {
                int nr = wn * 32 + fn * 8 + g;
                bfr[fn][0] = *(const uint32_t*)&B_s[nr * APAD + kb];
                bfr[fn][1] = *(const uint32_t*)&B_s[nr * APAD + kb + 8];
            }
            #pragma unroll
            for (int fm = 0; fm < 4; fm++)
                #pragma unroll
                for (int fn = 0; fn < 4; fn++)
                    hmma16816(c[fm][fn][0], c[fm][fn][1], c[fm][fn][2], c[fm][fn][3],
                              afr[fm][0], afr[fm][1], afr[fm][2], afr[fm][3],
                              bfr[fn][0], bfr[fn][1]);
        }
    }

    #pragma unroll
    for (int fn = 0; fn < 4; fn++) {
        int col = n0 + wn * 32 + fn * 8 + tig * 2;
        float2 bb = *(const float2*)(bf + col);
        #pragma unroll
        for (int fm = 0; fm < 4; fm++) {
            int r0 = m0 + wm * 64 + fm * 16 + g;
            float2 v0 = make_float2(c[fm][fn][0] + bb.x, c[fm][fn][1] + bb.y);
            float2 v1 = make_float2(c[fm][fn][2] + bb.x, c[fm][fn][3] + bb.y);
            *(float2*)(g_intern + (size_t)r0 * G4_SZ + col)       = v0;
            *(float2*)(g_intern + (size_t)(r0 + 8) * G4_SZ + col) = v1;
        }
    }
}

// ---------------------------------------------------------------------------
// Phase 2: persistent LSTM, HMMA recurrence v2.
// 16 warps = 2 n-groups (32 cols) x 8 k-splits (64 k).
// Wr-hi fragments live in REGISTERS (32/thread, loaded once); only Wr-lo is
// read from smem in pass 1. A-fragment duplication 2x (was 4x).
// Fold: 4 regions. Crossbar ~2.0K cyc < HMMA floor ~3.1K cyc.
// ---------------------------------------------------------------------------
#define THREADS 512
#define KPAD 520                      // bf16 per smem row (512 + 8)
#define SBL 0                         // Bl_s: 64*520*2 = 66560 B (also Bh temp)
#define SAH 66560                     // Ah_s: 32*520*2 = 33280 B
#define SAL 99840                     // Al_s: 33280 B
#define SMEM_BYTES 133120
#define ZROW 68                       // fold row stride (floats)
#define ZREG 2176                     // 32*68 floats per region (4 regions alias Ah+Al)

__global__ __launch_bounds__(THREADS, 1)
void lstm_persistent_kernel(const float* __restrict__ c0,
                            const float* __restrict__ iv,
                            const float* __restrict__ Wr,
                            float* __restrict__ Y,
                            float* __restrict__ C,
                            float* __restrict__ d_fin)
{
    extern __shared__ char sm[];
    unsigned short* Bl_s = (unsigned short*)(sm + SBL);
    unsigned short* Ah_s = (unsigned short*)(sm + SAH);
    unsigned short* Al_s = (unsigned short*)(sm + SAL);
    float* zbuf = (float*)(sm + SAH);   // 4 fold regions alias Ah+Al

    const int t    = threadIdx.x;
    const int bid  = blockIdx.x;
    const int j0   = (bid & 31) * 16;
    const int bm0  = (bid >> 5) * 32;
    const int grp  = bid >> 5;

    const int w    = t >> 5;
    const int lane = t & 31;
    const int ngrp = w & 1;            // n-group: cols [ngrp*32, +32)
    const int kq   = w >> 1;           // k-split: k [kq*64, +64)
    const int g8   = lane >> 2;
    const int tig  = lane & 3;

    // epilogue cell (one per thread)
    const int b_l = t >> 4, jl = t & 15;
    const int b_g = bm0 + b_l, j_g = j0 + jl;
    float c_reg = __ldcg(c0 + (size_t)b_g * D_SZ + j_g);

    // flags: warp w stages+consumes h k [32w, +32) -> producers j-blocks {2w, 2w+1}
    const unsigned fbase = g_flag[bid * 32];
    const unsigned* fp0 = &g_flag[(grp * 32 + 2 * w) * 32];
    const unsigned* fp1 = &g_flag[(grp * 32 + 2 * w + 1) * 32];

    // ---- init: stage Wr-hi to temp smem, load Bh fragments into registers
    #pragma unroll
    for (int u = 0; u < 16; u++) {
        int idx = u * THREADS + t;       // 8192 float4 slots = 512k x 64 cols
        int k  = idx >> 4;
        int g  = (idx >> 2) & 3;
        int jq = idx & 3;
        float4 v = __ldcg((const float4*)(Wr + (size_t)k * G4_SZ + g * D_SZ + j0 + jq * 4));
        const float* fv = &v.x;
        #pragma unroll
        for (int jj = 0; jj < 4; jj++) {
            __nv_bfloat16 hb = __float2bfloat16(fv[jj]);
            Bl_s[((jq * 4 + jj) * 4 + g) * KPAD + k] = *(unsigned short*)&hb;
        }
    }
    __syncthreads();

    uint32_t bh[4][4][2];   // [s][nt][2] Wr-hi fragments, persistent in regs
    #pragma unroll
    for (int s = 0; s < 4; s++)
        #pragma unroll
        for (int nt = 0; nt < 4; nt++) {
            int kb = kq * 64 + s * 16 + tig * 2;
            int nr = ngrp * 32 + nt * 8 + g8;
            bh[s][nt][0] = *(const uint32_t*)&Bl_s[nr * KPAD + kb];
            bh[s][nt][1] = *(const uint32_t*)&Bl_s[nr * KPAD + kb + 8];
        }
    __syncthreads();

    // ---- stage Wr-lo into Bl_s (persistent)
    #pragma unroll
    for (int u = 0; u < 16; u++) {
        int idx = u * THREADS + t;
        int k  = idx >> 4;
        int g  = (idx >> 2) & 3;
        int jq = idx & 3;
        float4 v = __ldcg((const float4*)(Wr + (size_t)k * G4_SZ + g * D_SZ + j0 + jq * 4));
        const float* fv = &v.x;
        #pragma unroll
        for (int jj = 0; jj < 4; jj++) {
            float f = fv[jj];
            __nv_bfloat16 hb = __float2bfloat16(f);
            float rem = f - __bfloat162float(hb);
            __nv_bfloat16 lb = __float2bfloat16(rem);
            Bl_s[((jq * 4 + jj) * 4 + g) * KPAD + k] = *(unsigned short*)&lb;
        }
    }
    __syncthreads();

    // h staging map: warp w stages k-slice [32w, +32) of all 32 b
    const int s_bb  = lane & 3;
    const int s_kqd = lane >> 2;

    // prefetch step 0 epilogue operands
    const float* itp = g_intern + (size_t)b_g * G4_SZ + j_g;
    float in0 = __ldcg(itp), in1 = __ldcg(itp + 512);
    float in2 = __ldcg(itp + 1024), in3 = __ldcg(itp + 1536);
    float mval = __ldcg(iv + b_g);

    for (int step = 0; step < T_STEPS; step++) {
        const uint32_t* hin = g_hpk[step & 1];
        uint32_t*       hot = g_hpk[(step + 1) & 1];

        // ---- wait for my 2 producers
        if (step > 0) {
            unsigned need = fbase + (unsigned)step;
            if ((int)(ld_acq(fp0) - need) < 0)
                do { __nanosleep(20); } while ((int)(ld_acq(fp0) - need) < 0);
            if ((int)(ld_acq(fp1) - need) < 0)
                do { __nanosleep(20); } while ((int)(ld_acq(fp1) - need) < 0);
        }

        // ---- stage h: unpack packed bf16 pairs into hi/lo planes
        {
            const uint32_t* base = hin + (size_t)bm0 * D_SZ + w * 32 + s_kqd * 4;
            #pragma unroll
            for (int u = 0; u < 8; u++) {
                int b = u * 4 + s_bb;
                uint4 v = __ldcg((const uint4*)(base + (size_t)b * D_SZ));
                uint32_t hi01 = __byte_perm(v.x, v.y, 0x5410);
                uint32_t lo01 = __byte_perm(v.x, v.y, 0x7632);
                uint32_t hi23 = __byte_perm(v.z, v.w, 0x5410);
                uint32_t lo23 = __byte_perm(v.z, v.w, 0x7632);
                int off = b * KPAD + w * 32 + s_kqd * 4;
                *(uint2*)&Ah_s[off] = make_uint2(hi01, hi23);
                *(uint2*)&Al_s[off] = make_uint2(lo01, lo23);
            }
        }
        __syncthreads();

        // ---- HMMA mainloop: passes (AhBh, AhBl, AlBh), 4 k16 steps each
        float c[2][4][4];
        #pragma unroll
        for (int mt = 0; mt < 2; mt++)
            #pragma unroll
            for (int nt = 0; nt < 4; nt++)
                #pragma unroll
                for (int q = 0; q < 4; q++) c[mt][nt][q] = 0.f;

        #pragma unroll
        for (int p = 0; p < 3; p++) {
            const unsigned short* As = (p == 2) ? Al_s : Ah_s;
            #pragma unroll
            for (int s = 0; s < 4; s++) {
                const int kb = kq * 64 + s * 16 + tig * 2;
                uint32_t afr[2][4];
                #pragma unroll
                for (int mt = 0; mt < 2; mt++) {
                    int r0 = mt * 16 + g8;
                    afr[mt][0] = *(const uint32_t*)&As[r0 * KPAD + kb];
                    afr[mt][1] = *(const uint32_t*)&As[(r0 + 8) * KPAD + kb];
                    afr[mt][2] = *(const uint32_t*)&As[r0 * KPAD + kb + 8];
                    afr[mt][3] = *(const uint32_t*)&As[(r0 + 8) * KPAD + kb + 8];
                }
                if (p == 1) {
                    #pragma unroll
                    for (int nt = 0; nt < 4; nt++) {
                        int nr = ngrp * 32 + nt * 8 + g8;
                        uint32_t b0 = *(const uint32_t*)&Bl_s[nr * KPAD + kb];
                        uint32_t b1 = *(const uint32_t*)&Bl_s[nr * KPAD + kb + 8];
                        #pragma unroll
                        for (int mt = 0; mt < 2; mt++)
                            hmma16816(c[mt][nt][0], c[mt][nt][1], c[mt][nt][2], c[mt][nt][3],
                                      afr[mt][0], afr[mt][1], afr[mt][2], afr[mt][3],
                                      b0, b1);
                    }
                } else {
                    #pragma unroll
                    for (int nt = 0; nt < 4; nt++)
                        #pragma unroll
                        for (int mt = 0; mt < 2; mt++)
                            hmma16816(c[mt][nt][0], c[mt][nt][1], c[mt][nt][2], c[mt][nt][3],
                                      afr[mt][0], afr[mt][1], afr[mt][2], afr[mt][3],
                                      bh[s][nt][0], bh[s][nt][1]);
                }
            }
        }

        // ---- fold: kq {4..7} store regions 0..3, kq {0..3} add in
        __syncthreads();
        if (kq >= 4) {
            float* z = zbuf + (kq - 4) * ZREG;
            #pragma unroll
            for (int mt = 0; mt < 2; mt++)
                #pragma unroll
                for (int nt = 0; nt < 4; nt++) {
                    int b = mt * 16 + g8;
                    int col = ngrp * 32 + nt * 8 + tig * 2;
                    *(float2*)&z[b * ZROW + col]       = make_float2(c[mt][nt][0], c[mt][nt][1]);
                    *(float2*)&z[(b + 8) * ZROW + col] = make_float2(c[mt][nt][2], c[mt][nt][3]);
                }
        }
        __syncthreads();
        if (kq < 4) {
            float* z = zbuf + kq * ZREG;
            #pragma unroll
            for (int mt = 0; mt < 2; mt++)
                #pragma unroll
                for (int nt = 0; nt < 4; nt++) {
                    int b = mt * 16 + g8;
                    int col = ngrp * 32 + nt * 8 + tig * 2;
                    float2 v0 = *(float2*)&z[b * ZROW + col];
                    float2 v1 = *(float2*)&z[(b + 8) * ZROW + col];
                    v0.x += c[mt][nt][0]; v0.y += c[mt][nt][1];
                    v1.x += c[mt][nt][2]; v1.y += c[mt][nt][3];
                    *(float2*)&z[b * ZROW + col]       = v0;
                    *(float2*)&z[(b + 8) * ZROW + col] = v1;
                }
        }
        __syncthreads();

        // ---- fused epilogue: one cell per thread (sum 4 regions)
        float y_out;
        {
            float4 z0 = *(const float4*)&zbuf[b_l * ZROW + jl * 4];
            float4 z1 = *(const float4*)&zbuf[ZREG + b_l * ZROW + jl * 4];
            float4 z2 = *(const float4*)&zbuf[2 * ZREG + b_l * ZROW + jl * 4];
            float4 z3 = *(const float4*)&zbuf[3 * ZREG + b_l * ZROW + jl * 4];

            float zc = z0.x + z1.x + z2.x + z3.x + in0;
            float zi = z0.y + z1.y + z2.y + z3.y + in1;
            float zf = z0.z + z1.z + z2.z + z3.z + in2;
            float zo = z0.w + z1.w + z2.w + z3.w + in3;

            zc = fminf(fmaxf(zc, -30.f), 30.f);
            float ec  = __expf(-2.f * zc);
            float cin = (1.f - ec) / (1.f + ec);
            float ig  = 1.f / (1.f + __expf(-zi));
            float fg  = 1.f / (1.f + __expf(-zf));
            float og  = 1.f / (1.f + __expf(-zo));

            float m    = mval;
            float cnew = m * (c_reg * fg + cin * ig) + (1.f - m) * c_reg;
            c_reg = cnew;
            float ct = fminf(fmaxf(cnew, -30.f), 30.f);
            float e2 = __expf(-2.f * ct);
            y_out = m * (og * (1.f - e2) / (1.f + e2));
        }

        // ---- publish h(step+1): packed bf16 split, coalesced STG.32
        if (step + 1 < T_STEPS)
            hot[(size_t)b_g * D_SZ + j_g] = pack_split(y_out);
        __syncthreads();
        if (step + 1 < T_STEPS && t == 0)
            st_release_exch(&g_flag[bid * 32], fbase + (unsigned)step + 1);

        // ---- deferred gmem writes
        {
            size_t o = (size_t)step * (B_SZ * D_SZ) + (size_t)b_g * D_SZ + j_g;
            Y[o] = y_out;
            C[o] = c_reg;
            if (step == T_STEPS - 1) d_fin[(size_t)b_g * D_SZ + j_g] = c_reg;
        }

        // ---- prefetch next step's epilogue operands
        if (step + 1 < T_STEPS) {
            const float* itn = g_intern + (size_t)(step + 1) * (B_SZ * G4_SZ)
                             + (size_t)b_g * G4_SZ + j_g;
            in0 = __ldcg(itn);
            in1 = __ldcg(itn + 512);
            in2 = __ldcg(itn + 1024);
            in3 = __ldcg(itn + 1536);
            mval = __ldcg(iv + (size_t)(step + 1) * B_SZ + b_g);
        }
    }
}

// ---------------------------------------------------------------------------
// Launch. Inputs: X, Wf, Wr, bf, i, h0, c0. Output: Y[T,B,D]|C[T,B,D]|d[B,D]
// ---------------------------------------------------------------------------
extern "C" void kernel_launch(void* const* d_in, const int* in_sizes, int n_in,
                              void* d_out, int out_size)
{
    (void)in_sizes; (void)n_in; (void)out_size;
    const float* X  = (const float*)d_in[0];
    const float* Wf = (const float*)d_in[1];
    const float* Wr = (const float*)d_in[2];
    const float* bf = (const float*)d_in[3];
    const float* iv = (const float*)d_in[4];
    const float* h0 = (const float*)d_in[5];
    const float* c0 = (const float*)d_in[6];

    float* out  = (float*)d_out;
    float* Y    = out;
    float* C    = out + (size_t)T_STEPS * B_SZ * D_SZ;
    float* dfin = C   + (size_t)T_STEPS * B_SZ * D_SZ;

    // one-time prep
    split_x_kernel<<<(T_STEPS * B_SZ * NI_SZ) / (4 * 256), 256>>>(X);
    split_wfT_kernel<<<(NI_SZ * G4_SZ) / 256, 256>>>(Wf);
    h0_pack_kernel<<<256, 256>>>(h0);

    // tensor-core GEMM: intern = X@Wf + bf
    dim3 gg(G4_SZ / 128, (T_STEPS * B_SZ) / 128);   // (16, 512)
    gemm_mma_kernel<<<gg, 256>>>(bf);

    // persistent HMMA recurrence
    cudaFuncSetAttribute(lstm_persistent_kernel,
                         cudaFuncAttributeMaxDynamicSharedMemorySize, SMEM_BYTES);
    lstm_persistent_kernel<<<128, THREADS, SMEM_BYTES>>>(
        c0, iv, Wr, Y, C, dfin);
}

// round 15
// speedup vs baseline: 1.1144x; 1.1144x over previous
#include <cuda_runtime.h>
#include <cuda_bf16.h>
#include <cstdint>
#include <math.h>

#define T_STEPS 512
#define B_SZ    128
#define NI_SZ   512
#define D_SZ    512
#define G4_SZ   2048   // 4*D

typedef unsigned long long u64;

// Scratch (device globals: allocation-free rule workaround)
__device__ float g_intern[(size_t)T_STEPS * B_SZ * G4_SZ];
__device__ uint32_t g_hpk[2][(size_t)B_SZ * D_SZ];   // packed bf16 hi|lo h, [b][k], ping-pong
__device__ unsigned g_flag[128 * 32];                // per-CTA produce flag (128B padded)
// bf16 split planes for the phase-1 GEMM
__device__ __nv_bfloat16 g_Xh[(size_t)T_STEPS * B_SZ * NI_SZ];
__device__ __nv_bfloat16 g_Xl[(size_t)T_STEPS * B_SZ * NI_SZ];
__device__ __nv_bfloat16 g_Bh[(size_t)G4_SZ * NI_SZ];   // Wf^T hi  [n][k]
__device__ __nv_bfloat16 g_Bl[(size_t)G4_SZ * NI_SZ];   // Wf^T lo

// ---------------- helpers ----------------
__device__ __forceinline__ unsigned ld_acq(const unsigned* p) {
    unsigned v;
    asm volatile("ld.acquire.gpu.global.u32 %0, [%1];" : "=r"(v) : "l"(p) : "memory");
    return v;
}
__device__ __forceinline__ void st_release(unsigned* p, unsigned v) {
    asm volatile("st.release.gpu.global.u32 [%0], %1;" :: "l"(p), "r"(v) : "memory");
}
__device__ __forceinline__ void hmma16816(float& c0, float& c1, float& c2, float& c3,
                                          uint32_t a0, uint32_t a1, uint32_t a2, uint32_t a3,
                                          uint32_t b0, uint32_t b1) {
    asm("mma.sync.aligned.m16n8k16.row.col.f32.bf16.bf16.f32 "
        "{%0,%1,%2,%3}, {%4,%5,%6,%7}, {%8,%9}, {%0,%1,%2,%3};"
        : "+f"(c0), "+f"(c1), "+f"(c2), "+f"(c3)
        : "r"(a0), "r"(a1), "r"(a2), "r"(a3), "r"(b0), "r"(b1));
}
__device__ __forceinline__ uint32_t pack_split(float f) {
    __nv_bfloat16 hb = __float2bfloat16(f);
    float rem = f - __bfloat162float(hb);
    __nv_bfloat16 lb = __float2bfloat16(rem);
    return (uint32_t)*(unsigned short*)&hb | ((uint32_t)*(unsigned short*)&lb << 16);
}
__device__ __forceinline__ uint32_t smem_u32(const void* p) {
    uint32_t a;
    asm("{ .reg .u64 t; cvta.to.shared.u64 t, %1; cvt.u32.u64 %0, t; }"
        : "=r"(a) : "l"(p));
    return a;
}
__device__ __forceinline__ void cp_async16(uint32_t dst, const void* src) {
    asm volatile("cp.async.cg.shared.global [%0], [%1], 16;" :: "r"(dst), "l"(src));
}

// ---------------------------------------------------------------------------
// One-time prep kernels
// ---------------------------------------------------------------------------
__global__ __launch_bounds__(256)
void split_x_kernel(const float* __restrict__ X)
{
    size_t i4 = (size_t)blockIdx.x * 256 + threadIdx.x;
    const float4 v = ((const float4*)X)[i4];
    float f[4] = {v.x, v.y, v.z, v.w};
    unsigned short h[4], l[4];
    #pragma unroll
    for (int q = 0; q < 4; q++) {
        __nv_bfloat16 hb = __float2bfloat16(f[q]);
        float lo = f[q] - __bfloat162float(hb);
        __nv_bfloat16 lb = __float2bfloat16(lo);
        h[q] = *(unsigned short*)&hb;
        l[q] = *(unsigned short*)&lb;
    }
    ((uint2*)g_Xh)[i4] = make_uint2((unsigned)h[0] | ((unsigned)h[1] << 16),
                                    (unsigned)h[2] | ((unsigned)h[3] << 16));
    ((uint2*)g_Xl)[i4] = make_uint2((unsigned)l[0] | ((unsigned)l[1] << 16),
                                    (unsigned)l[2] | ((unsigned)l[3] << 16));
}

__global__ __launch_bounds__(256)
void split_wfT_kernel(const float* __restrict__ Wf)
{
    int idx = blockIdx.x * 256 + threadIdx.x;
    int k = idx >> 11;
    int n = idx & 2047;
    float v = Wf[(size_t)k * G4_SZ + n];
    __nv_bfloat16 hb = __float2bfloat16(v);
    float lo = v - __bfloat162float(hb);
    g_Bh[(size_t)n * NI_SZ + k] = hb;
    g_Bl[(size_t)n * NI_SZ + k] = __float2bfloat16(lo);
}

__global__ __launch_bounds__(256)
void h0_pack_kernel(const float* __restrict__ h0)
{
    int idx = blockIdx.x * 256 + threadIdx.x;   // 65536
    g_hpk[0][idx] = pack_split(h0[idx]);
}

// ---------------------------------------------------------------------------
// Phase 1: intern = X@Wf + bf via mma.sync bf16 split GEMM, v2:
// cp.async double-buffered staging, 2 CTAs/SM (launch_bounds 256,2).
// ---------------------------------------------------------------------------
#define GAPAD 72
#define GTILE_U (128 * GAPAD)              // ushorts per tile (9216)
#define GSMEM_BYTES (4 * GTILE_U * 2)      // 2 bufs x (A+B) = 73728 B

__global__ __launch_bounds__(256, 2)
void gemm_mma_kernel(const float* __restrict__ bf)
{
    extern __shared__ unsigned short gsm[];
    const uint32_t sbase = smem_u32(gsm);

    const int t = threadIdx.x;
    const int wid = t >> 5, lane = t & 31;
    const int g  = lane >> 2;
    const int tig = lane & 3;
    const int n0 = blockIdx.x * 128;
    const int m0 = blockIdx.y * 128;
    const int wm = wid & 1;
    const int wn = wid >> 1;

    // staging indices (4 x 16B per tile per thread)
    const int s_row = t >> 1;              // base rows; full map per-u below

    float c[4][4][4];
    #pragma unroll
    for (int fm = 0; fm < 4; fm++)
        #pragma unroll
        for (int fn = 0; fn < 4; fn++)
            #pragma unroll
            for (int q = 0; q < 4; q++) c[fm][fn][q] = 0.f;

    // issue one chunk's cp.asyncs into buffer `buf`
    auto issue_chunk = [&](int cn, int buf) {
        int seg = cn >> 3;
        int k_in = (cn & 7) * 64;
        const unsigned short* Ap = (const unsigned short*)((seg < 2) ? g_Xh : g_Xl);
        const unsigned short* Bp = (const unsigned short*)((seg == 1) ? g_Bl : g_Bh);
        uint32_t abase = sbase + (uint32_t)buf * (2 * GTILE_U * 2);
        uint32_t bbase = abase + GTILE_U * 2;
        #pragma unroll
        for (int u = 0; u < 4; u++) {
            int idx = u * 256 + t;
            int row = idx >> 3;
            int kq8 = (idx & 7) * 8;
            cp_async16(abase + row * (GAPAD * 2) + kq8 * 2,
                       Ap + (size_t)(m0 + row) * NI_SZ + k_in + kq8);
            cp_async16(bbase + row * (GAPAD * 2) + kq8 * 2,
                       Bp + (size_t)(n0 + row) * NI_SZ + k_in + kq8);
        }
        asm volatile("cp.async.commit_group;" ::: "memory");
    };

    issue_chunk(0, 0);
    issue_chunk(1, 1);

    for (int ci = 0; ci < 24; ci++) {
        asm volatile("cp.async.wait_group 1;" ::: "memory");
        __syncthreads();

        const unsigned short* A_s = gsm + (ci & 1) * (2 * GTILE_U);
        const unsigned short* B_s = A_s + GTILE_U;

        #pragma unroll
        for (int ks = 0; ks < 4; ks++) {
            const int kb = ks * 16 + tig * 2;
            uint32_t afr[4][4], bfr[4][2];
            #pragma unroll
            for (int fm = 0; fm < 4; fm++) {
                int r0 = wm * 64 + fm * 16 + g;
                afr[fm][0] = *(const uint32_t*)&A_s[r0 * GAPAD + kb];
                afr[fm][1] = *(const uint32_t*)&A_s[(r0 + 8) * GAPAD + kb];
                afr[fm][2] = *(const uint32_t*)&A_s[r0 * GAPAD + kb + 8];
                afr[fm][3] = *(const uint32_t*)&A_s[(r0 + 8) * GAPAD + kb + 8];
            }
            #pragma unroll
            for (int fn = 0; fn < 4; fn++) {
                int nr = wn * 32 + fn * 8 + g;
                bfr[fn][0] = *(const uint32_t*)&B_s[nr * GAPAD + kb];
                bfr[fn][1] = *(const uint32_t*)&B_s[nr * GAPAD + kb + 8];
            }
            #pragma unroll
            for (int fm = 0; fm < 4; fm++)
                #pragma unroll
                for (int fn = 0; fn < 4; fn++)
                    hmma16816(c[fm][fn][0], c[fm][fn][1], c[fm][fn][2], c[fm][fn][3],
                              afr[fm][0], afr[fm][1], afr[fm][2], afr[fm][3],
                              bfr[fn][0], bfr[fn][1]);
        }
        __syncthreads();
        if (ci + 2 < 24)
            issue_chunk(ci + 2, ci & 1);
    }

    #pragma unroll
    for (int fn = 0; fn < 4; fn++) {
        int col = n0 + wn * 32 + fn * 8 + tig * 2;
        float2 bb = *(const float2*)(bf + col);
        #pragma unroll
        for (int fm = 0; fm < 4; fm++) {
            int r0 = m0 + wm * 64 + fm * 16 + g;
            float2 v0 = make_float2(c[fm][fn][0] + bb.x, c[fm][fn][1] + bb.y);
            float2 v1 = make_float2(c[fm][fn][2] + bb.x, c[fm][fn][3] + bb.y);
            *(float2*)(g_intern + (size_t)r0 * G4_SZ + col)       = v0;
            *(float2*)(g_intern + (size_t)(r0 + 8) * G4_SZ + col) = v1;
        }
    }
}

// ---------------------------------------------------------------------------
// Phase 2: persistent LSTM, HMMA recurrence v3.
// 16 warps = 2 n-groups (32 cols) x 8 k-splits (64 k). Wr-hi frags in regs.
// Fold: DEDICATED zbuf (no aliasing) -> single store phase, no pre-store
// sync (warp stores when its mainloop ends). 3 syncthreads/step (was 5).
// Flag release via st.release (no atomic round trip).
// ---------------------------------------------------------------------------
#define THREADS 512
#define KPAD 520                      // bf16 per smem row (512 + 8)
#define SBL 0                         // Bl_s: 64*520*2 = 66560 B (also Bh temp)
#define SAH 66560                     // Ah_s: 33280 B
#define SAL 99840                     // Al_s: 33280 B
#define SZB 133120                    // zbuf: 8 regions * 32*68*4 = 69632 B
#define SMEM_BYTES 202752
#define ZROW 68
#define ZREG 2176                     // floats per region

__global__ __launch_bounds__(THREADS, 1)
void lstm_persistent_kernel(const float* __restrict__ c0,
                            const float* __restrict__ iv,
                            const float* __restrict__ Wr,
                            float* __restrict__ Y,
                            float* __restrict__ C,
                            float* __restrict__ d_fin)
{
    extern __shared__ char sm[];
    unsigned short* Bl_s = (unsigned short*)(sm + SBL);
    unsigned short* Ah_s = (unsigned short*)(sm + SAH);
    unsigned short* Al_s = (unsigned short*)(sm + SAL);
    float* zbuf = (float*)(sm + SZB);

    const int t    = threadIdx.x;
    const int bid  = blockIdx.x;
    const int j0   = (bid & 31) * 16;
    const int bm0  = (bid >> 5) * 32;
    const int grp  = bid >> 5;

    const int w    = t >> 5;
    const int lane = t & 31;
    const int ngrp = w & 1;            // n-group: cols [ngrp*32, +32)
    const int kq   = w >> 1;           // k-split: k [kq*64, +64)
    const int g8   = lane >> 2;
    const int tig  = lane & 3;

    // epilogue cell (one per thread)
    const int b_l = t >> 4, jl = t & 15;
    const int b_g = bm0 + b_l, j_g = j0 + jl;
    float c_reg = __ldcg(c0 + (size_t)b_g * D_SZ + j_g);

    // flags: warp w stages+consumes h k [32w, +32) -> producers j-blocks {2w, 2w+1}
    const unsigned fbase = g_flag[bid * 32];
    const unsigned* fp0 = &g_flag[(grp * 32 + 2 * w) * 32];
    const unsigned* fp1 = &g_flag[(grp * 32 + 2 * w + 1) * 32];

    // ---- init: stage Wr-hi to temp smem, load Bh fragments into registers
    #pragma unroll
    for (int u = 0; u < 16; u++) {
        int idx = u * THREADS + t;
        int k  = idx >> 4;
        int g  = (idx >> 2) & 3;
        int jq = idx & 3;
        float4 v = __ldcg((const float4*)(Wr + (size_t)k * G4_SZ + g * D_SZ + j0 + jq * 4));
        const float* fv = &v.x;
        #pragma unroll
        for (int jj = 0; jj < 4; jj++) {
            __nv_bfloat16 hb = __float2bfloat16(fv[jj]);
            Bl_s[((jq * 4 + jj) * 4 + g) * KPAD + k] = *(unsigned short*)&hb;
        }
    }
    __syncthreads();

    uint32_t bh[4][4][2];   // Wr-hi fragments, persistent in regs
    #pragma unroll
    for (int s = 0; s < 4; s++)
        #pragma unroll
        for (int nt = 0; nt < 4; nt++) {
            int kb = kq * 64 + s * 16 + tig * 2;
            int nr = ngrp * 32 + nt * 8 + g8;
            bh[s][nt][0] = *(const uint32_t*)&Bl_s[nr * KPAD + kb];
            bh[s][nt][1] = *(const uint32_t*)&Bl_s[nr * KPAD + kb + 8];
        }
    __syncthreads();

    // ---- stage Wr-lo into Bl_s (persistent)
    #pragma unroll
    for (int u = 0; u < 16; u++) {
        int idx = u * THREADS + t;
        int k  = idx >> 4;
        int g  = (idx >> 2) & 3;
        int jq = idx & 3;
        float4 v = __ldcg((const float4*)(Wr + (size_t)k * G4_SZ + g * D_SZ + j0 + jq * 4));
        const float* fv = &v.x;
        #pragma unroll
        for (int jj = 0; jj < 4; jj++) {
            float f = fv[jj];
            __nv_bfloat16 hb = __float2bfloat16(f);
            float rem = f - __bfloat162float(hb);
            __nv_bfloat16 lb = __float2bfloat16(rem);
            Bl_s[((jq * 4 + jj) * 4 + g) * KPAD + k] = *(unsigned short*)&lb;
        }
    }
    __syncthreads();

    // h staging map: warp w stages k-slice [32w, +32) of all 32 b
    const int s_bb  = lane & 3;
    const int s_kqd = lane >> 2;

    // prefetch step 0 epilogue operands
    const float* itp = g_intern + (size_t)b_g * G4_SZ + j_g;
    float in0 = __ldcg(itp), in1 = __ldcg(itp + 512);
    float in2 = __ldcg(itp + 1024), in3 = __ldcg(itp + 1536);
    float mval = __ldcg(iv + b_g);

    for (int step = 0; step < T_STEPS; step++) {
        const uint32_t* hin = g_hpk[step & 1];
        uint32_t*       hot = g_hpk[(step + 1) & 1];

        // ---- wait for my 2 producers
        if (step > 0) {
            unsigned need = fbase + (unsigned)step;
            if ((int)(ld_acq(fp0) - need) < 0)
                do { __nanosleep(20); } while ((int)(ld_acq(fp0) - need) < 0);
            if ((int)(ld_acq(fp1) - need) < 0)
                do { __nanosleep(20); } while ((int)(ld_acq(fp1) - need) < 0);
        }

        // ---- stage h: unpack packed bf16 pairs into hi/lo planes
        {
            const uint32_t* base = hin + (size_t)bm0 * D_SZ + w * 32 + s_kqd * 4;
            #pragma unroll
            for (int u = 0; u < 8; u++) {
                int b = u * 4 + s_bb;
                uint4 v = __ldcg((const uint4*)(base + (size_t)b * D_SZ));
                uint32_t hi01 = __byte_perm(v.x, v.y, 0x5410);
                uint32_t lo01 = __byte_perm(v.x, v.y, 0x7632);
                uint32_t hi23 = __byte_perm(v.z, v.w, 0x5410);
                uint32_t lo23 = __byte_perm(v.z, v.w, 0x7632);
                int off = b * KPAD + w * 32 + s_kqd * 4;
                *(uint2*)&Ah_s[off] = make_uint2(hi01, hi23);
                *(uint2*)&Al_s[off] = make_uint2(lo01, lo23);
            }
        }
        __syncthreads();   // sync 1: all h staged

        // ---- HMMA mainloop: passes (AhBh, AhBl, AlBh)
        float c[2][4][4];
        #pragma unroll
        for (int mt = 0; mt < 2; mt++)
            #pragma unroll
            for (int nt = 0; nt < 4; nt++)
                #pragma unroll
                for (int q = 0; q < 4; q++) c[mt][nt][q] = 0.f;

        #pragma unroll
        for (int p = 0; p < 3; p++) {
            const unsigned short* As = (p == 2) ? Al_s : Ah_s;
            #pragma unroll
            for (int s = 0; s < 4; s++) {
                const int kb = kq * 64 + s * 16 + tig * 2;
                uint32_t afr[2][4];
                #pragma unroll
                for (int mt = 0; mt < 2; mt++) {
                    int r0 = mt * 16 + g8;
                    afr[mt][0] = *(const uint32_t*)&As[r0 * KPAD + kb];
                    afr[mt][1] = *(const uint32_t*)&As[(r0 + 8) * KPAD + kb];
                    afr[mt][2] = *(const uint32_t*)&As[r0 * KPAD + kb + 8];
                    afr[mt][3] = *(const uint32_t*)&As[(r0 + 8) * KPAD + kb + 8];
                }
                if (p == 1) {
                    #pragma unroll
                    for (int nt = 0; nt < 4; nt++) {
                        int nr = ngrp * 32 + nt * 8 + g8;
                        uint32_t b0 = *(const uint32_t*)&Bl_s[nr * KPAD + kb];
                        uint32_t b1 = *(const uint32_t*)&Bl_s[nr * KPAD + kb + 8];
                        #pragma unroll
                        for (int mt = 0; mt < 2; mt++)
                            hmma16816(c[mt][nt][0], c[mt][nt][1], c[mt][nt][2], c[mt][nt][3],
                                      afr[mt][0], afr[mt][1], afr[mt][2], afr[mt][3],
                                      b0, b1);
                    }
                } else {
                    #pragma unroll
                    for (int nt = 0; nt < 4; nt++)
                        #pragma unroll
                        for (int mt = 0; mt < 2; mt++)
                            hmma16816(c[mt][nt][0], c[mt][nt][1], c[mt][nt][2], c[mt][nt][3],
                                      afr[mt][0], afr[mt][1], afr[mt][2], afr[mt][3],
                                      bh[s][nt][0], bh[s][nt][1]);
                }
            }
        }

        // ---- fold: single store phase, NO pre-store sync (dedicated zbuf)
        {
            float* z = zbuf + kq * ZREG;
            #pragma unroll
            for (int mt = 0; mt < 2; mt++)
                #pragma unroll
                for (int nt = 0; nt < 4; nt++) {
                    int b = mt * 16 + g8;
                    int col = ngrp * 32 + nt * 8 + tig * 2;
                    *(float2*)&z[b * ZROW + col]       = make_float2(c[mt][nt][0], c[mt][nt][1]);
                    *(float2*)&z[(b + 8) * ZROW + col] = make_float2(c[mt][nt][2], c[mt][nt][3]);
                }
        }
        __syncthreads();   // sync 2: all partials stored

        // ---- fused epilogue: one cell per thread (sum 8 regions)
        float y_out;
        {
            const float* zp = zbuf + b_l * ZROW + jl * 4;
            float4 z0 = *(const float4*)(zp);
            float4 z1 = *(const float4*)(zp + ZREG);
            float4 z2 = *(const float4*)(zp + 2 * ZREG);
            float4 z3 = *(const float4*)(zp + 3 * ZREG);
            float4 z4 = *(const float4*)(zp + 4 * ZREG);
            float4 z5 = *(const float4*)(zp + 5 * ZREG);
            float4 z6 = *(const float4*)(zp + 6 * ZREG);
            float4 z7 = *(const float4*)(zp + 7 * ZREG);

            float zc = ((z0.x + z1.x) + (z2.x + z3.x)) + ((z4.x + z5.x) + (z6.x + z7.x)) + in0;
            float zi = ((z0.y + z1.y) + (z2.y + z3.y)) + ((z4.y + z5.y) + (z6.y + z7.y)) + in1;
            float zf = ((z0.z + z1.z) + (z2.z + z3.z)) + ((z4.z + z5.z) + (z6.z + z7.z)) + in2;
            float zo = ((z0.w + z1.w) + (z2.w + z3.w)) + ((z4.w + z5.w) + (z6.w + z7.w)) + in3;

            zc = fminf(fmaxf(zc, -30.f), 30.f);
            float ec  = __expf(-2.f * zc);
            float cin = (1.f - ec) / (1.f + ec);
            float ig  = 1.f / (1.f + __expf(-zi));
            float fg  = 1.f / (1.f + __expf(-zf));
            float og  = 1.f / (1.f + __expf(-zo));

            float m    = mval;
            float cnew = m * (c_reg * fg + cin * ig) + (1.f - m) * c_reg;
            c_reg = cnew;
            float ct = fminf(fmaxf(cnew, -30.f), 30.f);
            float e2 = __expf(-2.f * ct);
            y_out = m * (og * (1.f - e2) / (1.f + e2));
        }

        // ---- publish h(step+1): packed bf16 split, coalesced STG.32
        if (step + 1 < T_STEPS)
            hot[(size_t)b_g * D_SZ + j_g] = pack_split(y_out);
        __syncthreads();   // sync 3: hot STGs issued + zbuf reads done
        if (step + 1 < T_STEPS && t == 0)
            st_release(&g_flag[bid * 32], fbase + (unsigned)step + 1);

        // ---- deferred gmem writes
        {
            size_t o = (size_t)step * (B_SZ * D_SZ) + (size_t)b_g * D_SZ + j_g;
            Y[o] = y_out;
            C[o] = c_reg;
            if (step == T_STEPS - 1) d_fin[(size_t)b_g * D_SZ + j_g] = c_reg;
        }

        // ---- prefetch next step's epilogue operands
        if (step + 1 < T_STEPS) {
            const float* itn = g_intern + (size_t)(step + 1) * (B_SZ * G4_SZ)
                             + (size_t)b_g * G4_SZ + j_g;
            in0 = __ldcg(itn);
            in1 = __ldcg(itn + 512);
            in2 = __ldcg(itn + 1024);
            in3 = __ldcg(itn + 1536);
            mval = __ldcg(iv + (size_t)(step + 1) * B_SZ + b_g);
        }
    }
}

// ---------------------------------------------------------------------------
// Launch. Inputs: X, Wf, Wr, bf, i, h0, c0. Output: Y[T,B,D]|C[T,B,D]|d[B,D]
// ---------------------------------------------------------------------------
extern "C" void kernel_launch(void* const* d_in, const int* in_sizes, int n_in,
                              void* d_out, int out_size)
{
    (void)in_sizes; (void)n_in; (void)out_size;
    const float* X  = (const float*)d_in[0];
    const float* Wf = (const float*)d_in[1];
    const float* Wr = (const float*)d_in[2];
    const float* bf = (const float*)d_in[3];
    const float* iv = (const float*)d_in[4];
    const float* h0 = (const float*)d_in[5];
    const float* c0 = (const float*)d_in[6];

    float* out  = (float*)d_out;
    float* Y    = out;
    float* C    = out + (size_t)T_STEPS * B_SZ * D_SZ;
    float* dfin = C   + (size_t)T_STEPS * B_SZ * D_SZ;

    // one-time prep
    split_x_kernel<<<(T_STEPS * B_SZ * NI_SZ) / (4 * 256), 256>>>(X);
    split_wfT_kernel<<<(NI_SZ * G4_SZ) / 256, 256>>>(Wf);
    h0_pack_kernel<<<256, 256>>>(h0);

    // tensor-core GEMM: intern = X@Wf + bf (cp.async double-buffered)
    cudaFuncSetAttribute(gemm_mma_kernel,
                         cudaFuncAttributeMaxDynamicSharedMemorySize, GSMEM_BYTES);
    dim3 gg(G4_SZ / 128, (T_STEPS * B_SZ) / 128);   // (16, 512)
    gemm_mma_kernel<<<gg, 256, GSMEM_BYTES>>>(bf);

    // persistent HMMA recurrence
    cudaFuncSetAttribute(lstm_persistent_kernel,
                         cudaFuncAttributeMaxDynamicSharedMemorySize, SMEM_BYTES);
    lstm_persistent_kernel<<<128, THREADS, SMEM_BYTES>>>(
        c0, iv, Wr, Y, C, dfin);
}

// round 16
// speedup vs baseline: 1.1622x; 1.0429x over previous
#include <cuda_runtime.h>
#include <cuda_bf16.h>
#include <cstdint>
#include <math.h>

#define T_STEPS 512
#define B_SZ    128
#define NI_SZ   512
#define D_SZ    512
#define G4_SZ   2048   // 4*D

typedef unsigned long long u64;

// Scratch (device globals: allocation-free rule workaround)
__device__ float g_intern[(size_t)T_STEPS * B_SZ * G4_SZ];
__device__ uint32_t g_hpk[2][(size_t)B_SZ * D_SZ];   // packed bf16 hi|lo h, [b][k], ping-pong
__device__ unsigned g_flag[128 * 32];                // per-CTA produce flag (128B padded)
// bf16 split planes for the phase-1 GEMM
__device__ __nv_bfloat16 g_Xh[(size_t)T_STEPS * B_SZ * NI_SZ];
__device__ __nv_bfloat16 g_Xl[(size_t)T_STEPS * B_SZ * NI_SZ];
__device__ __nv_bfloat16 g_Bh[(size_t)G4_SZ * NI_SZ];   // Wf^T hi  [n][k]
__device__ __nv_bfloat16 g_Bl[(size_t)G4_SZ * NI_SZ];   // Wf^T lo

// ---------------- helpers ----------------
__device__ __forceinline__ unsigned ld_acq(const unsigned* p) {
    unsigned v;
    asm volatile("ld.acquire.gpu.global.u32 %0, [%1];" : "=r"(v) : "l"(p) : "memory");
    return v;
}
__device__ __forceinline__ void st_release(unsigned* p, unsigned v) {
    asm volatile("st.release.gpu.global.u32 [%0], %1;" :: "l"(p), "r"(v) : "memory");
}
__device__ __forceinline__ void hmma16816(float& c0, float& c1, float& c2, float& c3,
                                          uint32_t a0, uint32_t a1, uint32_t a2, uint32_t a3,
                                          uint32_t b0, uint32_t b1) {
    asm("mma.sync.aligned.m16n8k16.row.col.f32.bf16.bf16.f32 "
        "{%0,%1,%2,%3}, {%4,%5,%6,%7}, {%8,%9}, {%0,%1,%2,%3};"
        : "+f"(c0), "+f"(c1), "+f"(c2), "+f"(c3)
        : "r"(a0), "r"(a1), "r"(a2), "r"(a3), "r"(b0), "r"(b1));
}
__device__ __forceinline__ void ldsm_x4(uint32_t& r0, uint32_t& r1, uint32_t& r2, uint32_t& r3,
                                        uint32_t addr) {
    asm volatile("ldmatrix.sync.aligned.m8n8.x4.shared.b16 {%0,%1,%2,%3}, [%4];"
                 : "=r"(r0), "=r"(r1), "=r"(r2), "=r"(r3) : "r"(addr));
}
__device__ __forceinline__ uint32_t pack_split(float f) {
    __nv_bfloat16 hb = __float2bfloat16(f);
    float rem = f - __bfloat162float(hb);
    __nv_bfloat16 lb = __float2bfloat16(rem);
    return (uint32_t)*(unsigned short*)&hb | ((uint32_t)*(unsigned short*)&lb << 16);
}
__device__ __forceinline__ uint32_t smem_u32(const void* p) {
    uint32_t a;
    asm("{ .reg .u64 t; cvta.to.shared.u64 t, %1; cvt.u32.u64 %0, t; }"
        : "=r"(a) : "l"(p));
    return a;
}
__device__ __forceinline__ void cp_async16(uint32_t dst, const void* src) {
    asm volatile("cp.async.cg.shared.global [%0], [%1], 16;" :: "r"(dst), "l"(src));
}

// ---------------------------------------------------------------------------
// One-time prep kernels
// ---------------------------------------------------------------------------
__global__ __launch_bounds__(256)
void split_x_kernel(const float* __restrict__ X)
{
    size_t i4 = (size_t)blockIdx.x * 256 + threadIdx.x;
    const float4 v = ((const float4*)X)[i4];
    float f[4] = {v.x, v.y, v.z, v.w};
    unsigned short h[4], l[4];
    #pragma unroll
    for (int q = 0; q < 4; q++) {
        __nv_bfloat16 hb = __float2bfloat16(f[q]);
        float lo = f[q] - __bfloat162float(hb);
        __nv_bfloat16 lb = __float2bfloat16(lo);
        h[q] = *(unsigned short*)&hb;
        l[q] = *(unsigned short*)&lb;
    }
    ((uint2*)g_Xh)[i4] = make_uint2((unsigned)h[0] | ((unsigned)h[1] << 16),
                                    (unsigned)h[2] | ((unsigned)h[3] << 16));
    ((uint2*)g_Xl)[i4] = make_uint2((unsigned)l[0] | ((unsigned)l[1] << 16),
                                    (unsigned)l[2] | ((unsigned)l[3] << 16));
}

__global__ __launch_bounds__(256)
void split_wfT_kernel(const float* __restrict__ Wf)
{
    int idx = blockIdx.x * 256 + threadIdx.x;
    int k = idx >> 11;
    int n = idx & 2047;
    float v = Wf[(size_t)k * G4_SZ + n];
    __nv_bfloat16 hb = __float2bfloat16(v);
    float lo = v - __bfloat162float(hb);
    g_Bh[(size_t)n * NI_SZ + k] = hb;
    g_Bl[(size_t)n * NI_SZ + k] = __float2bfloat16(lo);
}

__global__ __launch_bounds__(256)
void h0_pack_kernel(const float* __restrict__ h0)
{
    int idx = blockIdx.x * 256 + threadIdx.x;   // 65536
    g_hpk[0][idx] = pack_split(h0[idx]);
}

// ---------------------------------------------------------------------------
// Phase 1: intern = X@Wf + bf via mma.sync bf16 split GEMM.
// cp.async double-buffered, 2 CTAs/SM, ldmatrix.x4 fragment loads.
// ---------------------------------------------------------------------------
#define GAPAD 72
#define GTILE_U (128 * GAPAD)              // ushorts per tile (9216)
#define GSMEM_BYTES (4 * GTILE_U * 2)      // 2 bufs x (A+B) = 73728 B

__global__ __launch_bounds__(256, 2)
void gemm_mma_kernel(const float* __restrict__ bf)
{
    extern __shared__ unsigned short gsm[];
    const uint32_t sbase = smem_u32(gsm);

    const int t = threadIdx.x;
    const int wid = t >> 5, lane = t & 31;
    const int g  = lane >> 2;
    const int tig = lane & 3;
    const int n0 = blockIdx.x * 128;
    const int m0 = blockIdx.y * 128;
    const int wm = wid & 1;
    const int wn = wid >> 1;

    // ldmatrix per-lane offsets (ushort units)
    const int lrow = lane & 7;
    const uint32_t a_off = (uint32_t)((wm * 64 + lrow + ((lane >> 3) & 1) * 8) * GAPAD
                                      + ((lane >> 4) & 1) * 8);
    const uint32_t b_off = (uint32_t)((wn * 32 + lrow + ((lane >> 4) & 1) * 8) * GAPAD
                                      + ((lane >> 3) & 1) * 8);

    float c[4][4][4];
    #pragma unroll
    for (int fm = 0; fm < 4; fm++)
        #pragma unroll
        for (int fn = 0; fn < 4; fn++)
            #pragma unroll
            for (int q = 0; q < 4; q++) c[fm][fn][q] = 0.f;

    auto issue_chunk = [&](int cn, int buf) {
        int seg = cn >> 3;
        int k_in = (cn & 7) * 64;
        const unsigned short* Ap = (const unsigned short*)((seg < 2) ? g_Xh : g_Xl);
        const unsigned short* Bp = (const unsigned short*)((seg == 1) ? g_Bl : g_Bh);
        uint32_t abase = sbase + (uint32_t)buf * (2 * GTILE_U * 2);
        uint32_t bbase = abase + GTILE_U * 2;
        #pragma unroll
        for (int u = 0; u < 4; u++) {
            int idx = u * 256 + t;
            int row = idx >> 3;
            int kq8 = (idx & 7) * 8;
            cp_async16(abase + row * (GAPAD * 2) + kq8 * 2,
                       Ap + (size_t)(m0 + row) * NI_SZ + k_in + kq8);
            cp_async16(bbase + row * (GAPAD * 2) + kq8 * 2,
                       Bp + (size_t)(n0 + row) * NI_SZ + k_in + kq8);
        }
        asm volatile("cp.async.commit_group;" ::: "memory");
    };

    issue_chunk(0, 0);
    issue_chunk(1, 1);

    for (int ci = 0; ci < 24; ci++) {
        asm volatile("cp.async.wait_group 1;" ::: "memory");
        __syncthreads();

        uint32_t Abase = sbase + (uint32_t)(ci & 1) * (2 * GTILE_U * 2);
        uint32_t Bbase = Abase + GTILE_U * 2;

        #pragma unroll
        for (int ks = 0; ks < 4; ks++) {
            uint32_t afr[4][4], bfr[4][2];
            #pragma unroll
            for (int fm = 0; fm < 4; fm++)
                ldsm_x4(afr[fm][0], afr[fm][1], afr[fm][2], afr[fm][3],
                        Abase + 2 * (a_off + (uint32_t)(fm * 16 * GAPAD + ks * 16)));
            #pragma unroll
            for (int fp = 0; fp < 2; fp++) {
                uint32_t b0, b1, b2, b3;
                ldsm_x4(b0, b1, b2, b3,
                        Bbase + 2 * (b_off + (uint32_t)(fp * 16 * GAPAD + ks * 16)));
                bfr[fp * 2][0] = b0;     bfr[fp * 2][1] = b1;
                bfr[fp * 2 + 1][0] = b2; bfr[fp * 2 + 1][1] = b3;
            }
            #pragma unroll
            for (int fm = 0; fm < 4; fm++)
                #pragma unroll
                for (int fn = 0; fn < 4; fn++)
                    hmma16816(c[fm][fn][0], c[fm][fn][1], c[fm][fn][2], c[fm][fn][3],
                              afr[fm][0], afr[fm][1], afr[fm][2], afr[fm][3],
                              bfr[fn][0], bfr[fn][1]);
        }
        __syncthreads();
        if (ci + 2 < 24)
            issue_chunk(ci + 2, ci & 1);
    }

    #pragma unroll
    for (int fn = 0; fn < 4; fn++) {
        int col = n0 + wn * 32 + fn * 8 + tig * 2;
        float2 bb = *(const float2*)(bf + col);
        #pragma unroll
        for (int fm = 0; fm < 4; fm++) {
            int r0 = m0 + wm * 64 + fm * 16 + g;
            float2 v0 = make_float2(c[fm][fn][0] + bb.x, c[fm][fn][1] + bb.y);
            float2 v1 = make_float2(c[fm][fn][2] + bb.x, c[fm][fn][3] + bb.y);
            *(float2*)(g_intern + (size_t)r0 * G4_SZ + col)       = v0;
            *(float2*)(g_intern + (size_t)(r0 + 8) * G4_SZ + col) = v1;
        }
    }
}

// ---------------------------------------------------------------------------
// Phase 2: persistent LSTM, HMMA recurrence v4.
// 16 warps = 2 n-groups x 8 k-splits. Wr-hi frags in regs, Wr-lo in smem.
// Stage-sync is PAIR-scoped (bar.sync 1+kq, 64): warps with fast producers
// start their mainloop immediately. Fold: single store into dedicated zbuf,
// one full sync, epilogue sums 8 regions. __fdividef epilogue, tight spin.
// ---------------------------------------------------------------------------
#define THREADS 512
#define KPAD 520                      // bf16 per smem row (512 + 8)
#define SBL 0                         // Bl_s: 64*520*2 = 66560 B (also Bh temp)
#define SAH 66560                     // Ah_s: 33280 B
#define SAL 99840                     // Al_s: 33280 B
#define SZB 133120                    // zbuf: 8 regions * 32*68*4 = 69632 B
#define SMEM_BYTES 202752
#define ZROW 68
#define ZREG 2176                     // floats per region

__global__ __launch_bounds__(THREADS, 1)
void lstm_persistent_kernel(const float* __restrict__ c0,
                            const float* __restrict__ iv,
                            const float* __restrict__ Wr,
                            float* __restrict__ Y,
                            float* __restrict__ C,
                            float* __restrict__ d_fin)
{
    extern __shared__ char sm[];
    unsigned short* Bl_s = (unsigned short*)(sm + SBL);
    unsigned short* Ah_s = (unsigned short*)(sm + SAH);
    unsigned short* Al_s = (unsigned short*)(sm + SAL);
    float* zbuf = (float*)(sm + SZB);

    const int t    = threadIdx.x;
    const int bid  = blockIdx.x;
    const int j0   = (bid & 31) * 16;
    const int bm0  = (bid >> 5) * 32;
    const int grp  = bid >> 5;

    const int w    = t >> 5;
    const int lane = t & 31;
    const int ngrp = w & 1;            // n-group: cols [ngrp*32, +32)
    const int kq   = w >> 1;           // k-split: k [kq*64, +64)
    const int g8   = lane >> 2;
    const int tig  = lane & 3;

    // epilogue cell (one per thread)
    const int b_l = t >> 4, jl = t & 15;
    const int b_g = bm0 + b_l, j_g = j0 + jl;
    float c_reg = __ldcg(c0 + (size_t)b_g * D_SZ + j_g);

    // flags: warp w stages+consumes h k [32w, +32) -> producers j-blocks {2w, 2w+1}
    const unsigned fbase = g_flag[bid * 32];
    const unsigned* fp0 = &g_flag[(grp * 32 + 2 * w) * 32];
    const unsigned* fp1 = &g_flag[(grp * 32 + 2 * w + 1) * 32];

    // ---- init: stage Wr-hi to temp smem, load Bh fragments into registers
    #pragma unroll
    for (int u = 0; u < 16; u++) {
        int idx = u * THREADS + t;
        int k  = idx >> 4;
        int g  = (idx >> 2) & 3;
        int jq = idx & 3;
        float4 v = __ldcg((const float4*)(Wr + (size_t)k * G4_SZ + g * D_SZ + j0 + jq * 4));
        const float* fv = &v.x;
        #pragma unroll
        for (int jj = 0; jj < 4; jj++) {
            __nv_bfloat16 hb = __float2bfloat16(fv[jj]);
            Bl_s[((jq * 4 + jj) * 4 + g) * KPAD + k] = *(unsigned short*)&hb;
        }
    }
    __syncthreads();

    uint32_t bh[4][4][2];   // Wr-hi fragments, persistent in regs
    #pragma unroll
    for (int s = 0; s < 4; s++)
        #pragma unroll
        for (int nt = 0; nt < 4; nt++) {
            int kb = kq * 64 + s * 16 + tig * 2;
            int nr = ngrp * 32 + nt * 8 + g8;
            bh[s][nt][0] = *(const uint32_t*)&Bl_s[nr * KPAD + kb];
            bh[s][nt][1] = *(const uint32_t*)&Bl_s[nr * KPAD + kb + 8];
        }
    __syncthreads();

    // ---- stage Wr-lo into Bl_s (persistent)
    #pragma unroll
    for (int u = 0; u < 16; u++) {
        int idx = u * THREADS + t;
        int k  = idx >> 4;
        int g  = (idx >> 2) & 3;
        int jq = idx & 3;
        float4 v = __ldcg((const float4*)(Wr + (size_t)k * G4_SZ + g * D_SZ + j0 + jq * 4));
        const float* fv = &v.x;
        #pragma unroll
        for (int jj = 0; jj < 4; jj++) {
            float f = fv[jj];
            __nv_bfloat16 hb = __float2bfloat16(f);
            float rem = f - __bfloat162float(hb);
            __nv_bfloat16 lb = __float2bfloat16(rem);
            Bl_s[((jq * 4 + jj) * 4 + g) * KPAD + k] = *(unsigned short*)&lb;
        }
    }
    __syncthreads();

    // h staging map: warp w stages k-slice [32w, +32) of all 32 b
    const int s_bb  = lane & 3;
    const int s_kqd = lane >> 2;

    // prefetch step 0 epilogue operands
    const float* itp = g_intern + (size_t)b_g * G4_SZ + j_g;
    float in0 = __ldcg(itp), in1 = __ldcg(itp + 512);
    float in2 = __ldcg(itp + 1024), in3 = __ldcg(itp + 1536);
    float mval = __ldcg(iv + b_g);

    for (int step = 0; step < T_STEPS; step++) {
        const uint32_t* hin = g_hpk[step & 1];
        uint32_t*       hot = g_hpk[(step + 1) & 1];

        // ---- wait for my 2 producers (tight spin)
        if (step > 0) {
            unsigned need = fbase + (unsigned)step;
            while ((int)(ld_acq(fp0) - need) < 0) {}
            while ((int)(ld_acq(fp1) - need) < 0) {}
        }

        // ---- stage h: unpack packed bf16 pairs into hi/lo planes
        {
            const uint32_t* base = hin + (size_t)bm0 * D_SZ + w * 32 + s_kqd * 4;
            #pragma unroll
            for (int u = 0; u < 8; u++) {
                int b = u * 4 + s_bb;
                uint4 v = __ldcg((const uint4*)(base + (size_t)b * D_SZ));
                uint32_t hi01 = __byte_perm(v.x, v.y, 0x5410);
                uint32_t lo01 = __byte_perm(v.x, v.y, 0x7632);
                uint32_t hi23 = __byte_perm(v.z, v.w, 0x5410);
                uint32_t lo23 = __byte_perm(v.z, v.w, 0x7632);
                int off = b * KPAD + w * 32 + s_kqd * 4;
                *(uint2*)&Ah_s[off] = make_uint2(hi01, hi23);
                *(uint2*)&Al_s[off] = make_uint2(lo01, lo23);
            }
        }
        // pair-scoped: warps (2kq, 2kq+1) staged rows [64kq, +64) they consume
        asm volatile("bar.sync %0, 64;" :: "r"(1 + kq) : "memory");

        // ---- HMMA mainloop: passes (AhBh, AhBl, AlBh)
        float c[2][4][4];
        #pragma unroll
        for (int mt = 0; mt < 2; mt++)
            #pragma unroll
            for (int nt = 0; nt < 4; nt++)
                #pragma unroll
                for (int q = 0; q < 4; q++) c[mt][nt][q] = 0.f;

        #pragma unroll
        for (int p = 0; p < 3; p++) {
            const unsigned short* As = (p == 2) ? Al_s : Ah_s;
            #pragma unroll
            for (int s = 0; s < 4; s++) {
                const int kb = kq * 64 + s * 16 + tig * 2;
                uint32_t afr[2][4];
                #pragma unroll
                for (int mt = 0; mt < 2; mt++) {
                    int r0 = mt * 16 + g8;
                    afr[mt][0] = *(const uint32_t*)&As[r0 * KPAD + kb];
                    afr[mt][1] = *(const uint32_t*)&As[(r0 + 8) * KPAD + kb];
                    afr[mt][2] = *(const uint32_t*)&As[r0 * KPAD + kb + 8];
                    afr[mt][3] = *(const uint32_t*)&As[(r0 + 8) * KPAD + kb + 8];
                }
                if (p == 1) {
                    #pragma unroll
                    for (int nt = 0; nt < 4; nt++) {
                        int nr = ngrp * 32 + nt * 8 + g8;
                        uint32_t b0 = *(const uint32_t*)&Bl_s[nr * KPAD + kb];
                        uint32_t b1 = *(const uint32_t*)&Bl_s[nr * KPAD + kb + 8];
                        #pragma unroll
                        for (int mt = 0; mt < 2; mt++)
                            hmma16816(c[mt][nt][0], c[mt][nt][1], c[mt][nt][2], c[mt][nt][3],
                                      afr[mt][0], afr[mt][1], afr[mt][2], afr[mt][3],
                                      b0, b1);
                    }
                } else {
                    #pragma unroll
                    for (int nt = 0; nt < 4; nt++)
                        #pragma unroll
                        for (int mt = 0; mt < 2; mt++)
                            hmma16816(c[mt][nt][0], c[mt][nt][1], c[mt][nt][2], c[mt][nt][3],
                                      afr[mt][0], afr[mt][1], afr[mt][2], afr[mt][3],
                                      bh[s][nt][0], bh[s][nt][1]);
                }
            }
        }

        // ---- fold: single store phase, no pre-store sync (dedicated zbuf)
        {
            float* z = zbuf + kq * ZREG;
            #pragma unroll
            for (int mt = 0; mt < 2; mt++)
                #pragma unroll
                for (int nt = 0; nt < 4; nt++) {
                    int b = mt * 16 + g8;
                    int col = ngrp * 32 + nt * 8 + tig * 2;
                    *(float2*)&z[b * ZROW + col]       = make_float2(c[mt][nt][0], c[mt][nt][1]);
                    *(float2*)&z[(b + 8) * ZROW + col] = make_float2(c[mt][nt][2], c[mt][nt][3]);
                }
        }
        __syncthreads();   // all partials stored

        // ---- fused epilogue: one cell per thread (sum 8 regions)
        float y_out;
        {
            const float* zp = zbuf + b_l * ZROW + jl * 4;
            float4 z0 = *(const float4*)(zp);
            float4 z1 = *(const float4*)(zp + ZREG);
            float4 z2 = *(const float4*)(zp + 2 * ZREG);
            float4 z3 = *(const float4*)(zp + 3 * ZREG);
            float4 z4 = *(const float4*)(zp + 4 * ZREG);
            float4 z5 = *(const float4*)(zp + 5 * ZREG);
            float4 z6 = *(const float4*)(zp + 6 * ZREG);
            float4 z7 = *(const float4*)(zp + 7 * ZREG);

            float zc = ((z0.x + z1.x) + (z2.x + z3.x)) + ((z4.x + z5.x) + (z6.x + z7.x)) + in0;
            float zi = ((z0.y + z1.y) + (z2.y + z3.y)) + ((z4.y + z5.y) + (z6.y + z7.y)) + in1;
            float zf = ((z0.z + z1.z) + (z2.z + z3.z)) + ((z4.z + z5.z) + (z6.z + z7.z)) + in2;
            float zo = ((z0.w + z1.w) + (z2.w + z3.w)) + ((z4.w + z5.w) + (z6.w + z7.w)) + in3;

            zc = fminf(fmaxf(zc, -30.f), 30.f);
            float ec  = __expf(-2.f * zc);
            float cin = __fdividef(1.f - ec, 1.f + ec);
            float ig  = __fdividef(1.f, 1.f + __expf(-zi));
            float fg  = __fdividef(1.f, 1.f + __expf(-zf));
            float og  = __fdividef(1.f, 1.f + __expf(-zo));

            float m    = mval;
            float cnew = m * (c_reg * fg + cin * ig) + (1.f - m) * c_reg;
            c_reg = cnew;
            float ct = fminf(fmaxf(cnew, -30.f), 30.f);
            float e2 = __expf(-2.f * ct);
            y_out = m * (og * __fdividef(1.f - e2, 1.f + e2));
        }

        // ---- publish h(step+1): packed bf16 split, coalesced STG.32
        if (step + 1 < T_STEPS)
            hot[(size_t)b_g * D_SZ + j_g] = pack_split(y_out);
        __syncthreads();   // hot STGs issued + zbuf reads done
        if (step + 1 < T_STEPS && t == 0)
            st_release(&g_flag[bid * 32], fbase + (unsigned)step + 1);

        // ---- deferred gmem writes
        {
            size_t o = (size_t)step * (B_SZ * D_SZ) + (size_t)b_g * D_SZ + j_g;
            Y[o] = y_out;
            C[o] = c_reg;
            if (step == T_STEPS - 1) d_fin[(size_t)b_g * D_SZ + j_g] = c_reg;
        }

        // ---- prefetch next step's epilogue operands
        if (step + 1 < T_STEPS) {
            const float* itn = g_intern + (size_t)(step + 1) * (B_SZ * G4_SZ)
                             + (size_t)b_g * G4_SZ + j_g;
            in0 = __ldcg(itn);
            in1 = __ldcg(itn + 512);
            in2 = __ldcg(itn + 1024);
            in3 = __ldcg(itn + 1536);
            mval = __ldcg(iv + (size_t)(step + 1) * B_SZ + b_g);
        }
    }
}

// ---------------------------------------------------------------------------
// Launch. Inputs: X, Wf, Wr, bf, i, h0, c0. Output: Y[T,B,D]|C[T,B,D]|d[B,D]
// ---------------------------------------------------------------------------
extern "C" void kernel_launch(void* const* d_in, const int* in_sizes, int n_in,
                              void* d_out, int out_size)
{
    (void)in_sizes; (void)n_in; (void)out_size;
    const float* X  = (const float*)d_in[0];
    const float* Wf = (const float*)d_in[1];
    const float* Wr = (const float*)d_in[2];
    const float* bf = (const float*)d_in[3];
    const float* iv = (const float*)d_in[4];
    const float* h0 = (const float*)d_in[5];
    const float* c0 = (const float*)d_in[6];

    float* out  = (float*)d_out;
    float* Y    = out;
    float* C    = out + (size_t)T_STEPS * B_SZ * D_SZ;
    float* dfin = C   + (size_t)T_STEPS * B_SZ * D_SZ;

    // one-time prep
    split_x_kernel<<<(T_STEPS * B_SZ * NI_SZ) / (4 * 256), 256>>>(X);
    split_wfT_kernel<<<(NI_SZ * G4_SZ) / 256, 256>>>(Wf);
    h0_pack_kernel<<<256, 256>>>(h0);

    // tensor-core GEMM: intern = X@Wf + bf
    cudaFuncSetAttribute(gemm_mma_kernel,
                         cudaFuncAttributeMaxDynamicSharedMemorySize, GSMEM_BYTES);
    dim3 gg(G4_SZ / 128, (T_STEPS * B_SZ) / 128);   // (16, 512)
    gemm_mma_kernel<<<gg, 256, GSMEM_BYTES>>>(bf);

    // persistent HMMA recurrence
    cudaFuncSetAttribute(lstm_persistent_kernel,
                         cudaFuncAttributeMaxDynamicSharedMemorySize, SMEM_BYTES);
    lstm_persistent_kernel<<<128, THREADS, SMEM_BYTES>>>(
        c0, iv, Wr, Y, C, dfin);
}